// round 9
// baseline (speedup 1.0000x reference)
#include <cuda_runtime.h>

#define NBLK 1184   // 148 SMs x 8 blocks: one wave
#define NTHR 256
#define CHUNK4 (2 * NTHR)   // float4 elements per work chunk (512 -> 8KB/array)

// Device scratch (no cudaMalloc allowed). Both counters self-reset:
//  - g_chunk: exactly NCHUNK + NBLK atomicInc per launch (each block consumes
//    exactly one stop ticket), wrap value makes it return to 0 every launch.
//  - g_count: wraps at NBLK.
__device__ unsigned int g_chunk;
__device__ float g_part[NBLK];
__device__ unsigned int g_count;

// LDG.128 with 256B L2 prefetch-granularity hint: halves LTS request count
// and improves DRAM row-buffer locality on this pure-streaming pattern.
__device__ __forceinline__ float4 ldg256(const float4* p) {
    float4 v;
    asm("ld.global.nc.L2::256B.v4.f32 {%0,%1,%2,%3}, [%4];"
        : "=f"(v.x), "=f"(v.y), "=f"(v.z), "=f"(v.w)
        : "l"(p));
    return v;
}

__global__ void __launch_bounds__(NTHR)
mse_kernel(const float* __restrict__ in,
           const float* __restrict__ tg,
           float* __restrict__ out,
           int n) {
    const float4* __restrict__ in4 = (const float4*)in;
    const float4* __restrict__ tg4 = (const float4*)tg;
    const int n4 = n >> 2;

    const unsigned nchunk = (unsigned)((n4 + CHUNK4 - 1) / CHUNK4);
    const unsigned wrapv  = nchunk + NBLK - 1;  // atomicInc wrap boundary

    __shared__ unsigned s_next[2];
    float acc0 = 0.0f, acc1 = 0.0f;

    // Dynamic work-stealing: grab chunks of CHUNK4 float4s. Double-buffered
    // id prefetch hides the atomic latency behind the chunk's loads.
    if (threadIdx.x == 0) s_next[0] = atomicInc(&g_chunk, wrapv);
    __syncthreads();
    unsigned cur = s_next[0];
    int buf = 1;

    while (cur < nchunk) {
        if (threadIdx.x == 0) s_next[buf] = atomicInc(&g_chunk, wrapv);

        int base = (int)cur * CHUNK4 + threadIdx.x;
        int i0 = base;
        int i1 = base + NTHR;
        if (i1 < n4) {  // full chunk (the common case)
            float4 a0 = ldg256(&in4[i0]);
            float4 a1 = ldg256(&in4[i1]);
            float4 b0 = ldg256(&tg4[i0]);
            float4 b1 = ldg256(&tg4[i1]);
            float d;
            d = a0.x - b0.x; acc0 = fmaf(d, d, acc0);
            d = a0.y - b0.y; acc1 = fmaf(d, d, acc1);
            d = a0.z - b0.z; acc0 = fmaf(d, d, acc0);
            d = a0.w - b0.w; acc1 = fmaf(d, d, acc1);
            d = a1.x - b1.x; acc0 = fmaf(d, d, acc0);
            d = a1.y - b1.y; acc1 = fmaf(d, d, acc1);
            d = a1.z - b1.z; acc0 = fmaf(d, d, acc0);
            d = a1.w - b1.w; acc1 = fmaf(d, d, acc1);
        } else {  // partial tail chunk
            for (int i = i0; i < n4; i += NTHR) {
                float4 a = __ldg(&in4[i]);
                float4 b = __ldg(&tg4[i]);
                float d;
                d = a.x - b.x; acc0 = fmaf(d, d, acc0);
                d = a.y - b.y; acc1 = fmaf(d, d, acc1);
                d = a.z - b.z; acc0 = fmaf(d, d, acc0);
                d = a.w - b.w; acc1 = fmaf(d, d, acc1);
            }
        }

        __syncthreads();   // s_next[buf] now valid for everyone
        cur = s_next[buf];
        buf ^= 1;
    }

    float acc = acc0 + acc1;

    // Warp reduction
    #pragma unroll
    for (int off = 16; off > 0; off >>= 1)
        acc += __shfl_xor_sync(0xFFFFFFFFu, acc, off);

    __shared__ float warp_sums[NTHR / 32];
    int lane = threadIdx.x & 31;
    int wid  = threadIdx.x >> 5;
    if (lane == 0) warp_sums[wid] = acc;
    __syncthreads();

    __shared__ bool is_last;
    if (wid == 0) {
        float v = (lane < NTHR / 32) ? warp_sums[lane] : 0.0f;
        #pragma unroll
        for (int off = 16; off > 0; off >>= 1)
            v += __shfl_xor_sync(0xFFFFFFFFu, v, off);
        if (lane == 0) {
            g_part[blockIdx.x] = v;
            __threadfence();
            unsigned old = atomicInc(&g_count, NBLK - 1);  // wraps -> replay-safe
            is_last = (old == NBLK - 1);
        }
    }
    __syncthreads();

    if (!is_last) return;

    // ── Last block: reduce the 1184 partials in double + finalize ──
    __threadfence();  // acquire: make all blocks' g_part writes visible

    double s = 0.0;
    for (int k = threadIdx.x; k < NBLK; k += NTHR)
        s += (double)g_part[k];

    #pragma unroll
    for (int off = 16; off > 0; off >>= 1)
        s += __shfl_xor_sync(0xFFFFFFFFu, s, off);

    __shared__ double dsums[NTHR / 32];
    if (lane == 0) dsums[wid] = s;
    __syncthreads();

    if (threadIdx.x == 0) {
        double total = 0.0;
        #pragma unroll
        for (int w = 0; w < NTHR / 32; w++) total += dsums[w];

        // Element-0 conditional rescale, applied analytically.
        float d0 = fabsf(in[0] - tg[0]);
        bool hit = (d0 == 3.0f) || (d0 == 4.0f) || (d0 == 5.0f) || (d0 == 6.0f);
        float d0a = hit ? d0 * 0.8f : d0;
        total += (double)d0a * (double)d0a - (double)d0 * (double)d0;

        out[0] = (float)(total / (double)n);
    }
}

extern "C" void kernel_launch(void* const* d_in, const int* in_sizes, int n_in,
                              void* d_out, int out_size) {
    const float* in = (const float*)d_in[0];
    const float* tg = (const float*)d_in[1];
    float* out = (float*)d_out;
    int n = in_sizes[0];

    mse_kernel<<<NBLK, NTHR>>>(in, tg, out, n);
}

// round 10
// speedup vs baseline: 1.0878x; 1.0878x over previous
#include <cuda_runtime.h>

#define NBLK 1184   // 148 SMs x 8 blocks: one wave
#define NTHR 256
#define TRIPS 4                  // sequential 4KB sub-trips per chunk
#define CHUNK4 (TRIPS * NTHR)    // 1024 float4 = 16KB per array per chunk

// Device scratch (no cudaMalloc allowed). Both counters self-reset:
//  - g_chunk: exactly NCHUNK + NBLK atomicInc per launch (each block consumes
//    exactly one stop ticket), wrap value makes it return to 0 every launch.
//  - g_count: wraps at NBLK.
__device__ unsigned int g_chunk;
__device__ float g_part[NBLK];
__device__ unsigned int g_count;

__global__ void __launch_bounds__(NTHR)
mse_kernel(const float* __restrict__ in,
           const float* __restrict__ tg,
           float* __restrict__ out,
           int n) {
    const float4* __restrict__ in4 = (const float4*)in;
    const float4* __restrict__ tg4 = (const float4*)tg;
    const int n4 = n >> 2;

    const unsigned nchunk = (unsigned)((n4 + CHUNK4 - 1) / CHUNK4);
    const unsigned wrapv  = nchunk + NBLK - 1;  // atomicInc wrap boundary

    __shared__ unsigned s_next[2];
    float acc0 = 0.0f, acc1 = 0.0f;

    // Dynamic work-stealing over 16KB-per-array chunks: long sequential runs
    // for DRAM row-buffer locality, ~7 chunks/block for balance. Double-
    // buffered id prefetch hides the atomic latency behind the chunk's loads.
    if (threadIdx.x == 0) s_next[0] = atomicInc(&g_chunk, wrapv);
    __syncthreads();
    unsigned cur = s_next[0];
    int buf = 1;

    while (cur < nchunk) {
        if (threadIdx.x == 0) s_next[buf] = atomicInc(&g_chunk, wrapv);

        int base = (int)cur * CHUNK4 + threadIdx.x;
        if (base + (TRIPS - 1) * NTHR < n4) {  // full chunk (common case)
            #pragma unroll
            for (int t = 0; t < TRIPS; t += 2) {
                int i0 = base + t * NTHR;
                int i1 = base + (t + 1) * NTHR;
                float4 a0 = __ldg(&in4[i0]);
                float4 a1 = __ldg(&in4[i1]);
                float4 b0 = __ldg(&tg4[i0]);
                float4 b1 = __ldg(&tg4[i1]);
                float d;
                d = a0.x - b0.x; acc0 = fmaf(d, d, acc0);
                d = a0.y - b0.y; acc1 = fmaf(d, d, acc1);
                d = a0.z - b0.z; acc0 = fmaf(d, d, acc0);
                d = a0.w - b0.w; acc1 = fmaf(d, d, acc1);
                d = a1.x - b1.x; acc0 = fmaf(d, d, acc0);
                d = a1.y - b1.y; acc1 = fmaf(d, d, acc1);
                d = a1.z - b1.z; acc0 = fmaf(d, d, acc0);
                d = a1.w - b1.w; acc1 = fmaf(d, d, acc1);
            }
        } else {  // partial tail chunk
            for (int i = base; i < n4; i += NTHR) {
                float4 a = __ldg(&in4[i]);
                float4 b = __ldg(&tg4[i]);
                float d;
                d = a.x - b.x; acc0 = fmaf(d, d, acc0);
                d = a.y - b.y; acc1 = fmaf(d, d, acc1);
                d = a.z - b.z; acc0 = fmaf(d, d, acc0);
                d = a.w - b.w; acc1 = fmaf(d, d, acc1);
            }
        }

        __syncthreads();   // s_next[buf] now valid for everyone
        cur = s_next[buf];
        buf ^= 1;
    }

    float acc = acc0 + acc1;

    // Warp reduction
    #pragma unroll
    for (int off = 16; off > 0; off >>= 1)
        acc += __shfl_xor_sync(0xFFFFFFFFu, acc, off);

    __shared__ float warp_sums[NTHR / 32];
    int lane = threadIdx.x & 31;
    int wid  = threadIdx.x >> 5;
    if (lane == 0) warp_sums[wid] = acc;
    __syncthreads();

    __shared__ bool is_last;
    if (wid == 0) {
        float v = (lane < NTHR / 32) ? warp_sums[lane] : 0.0f;
        #pragma unroll
        for (int off = 16; off > 0; off >>= 1)
            v += __shfl_xor_sync(0xFFFFFFFFu, v, off);
        if (lane == 0) {
            g_part[blockIdx.x] = v;
            __threadfence();
            unsigned old = atomicInc(&g_count, NBLK - 1);  // wraps -> replay-safe
            is_last = (old == NBLK - 1);
        }
    }
    __syncthreads();

    if (!is_last) return;

    // ── Last block: reduce the 1184 partials in double + finalize ──
    __threadfence();  // acquire: make all blocks' g_part writes visible

    double s = 0.0;
    for (int k = threadIdx.x; k < NBLK; k += NTHR)
        s += (double)g_part[k];

    #pragma unroll
    for (int off = 16; off > 0; off >>= 1)
        s += __shfl_xor_sync(0xFFFFFFFFu, s, off);

    __shared__ double dsums[NTHR / 32];
    if (lane == 0) dsums[wid] = s;
    __syncthreads();

    if (threadIdx.x == 0) {
        double total = 0.0;
        #pragma unroll
        for (int w = 0; w < NTHR / 32; w++) total += dsums[w];

        // Element-0 conditional rescale, applied analytically.
        float d0 = fabsf(in[0] - tg[0]);
        bool hit = (d0 == 3.0f) || (d0 == 4.0f) || (d0 == 5.0f) || (d0 == 6.0f);
        float d0a = hit ? d0 * 0.8f : d0;
        total += (double)d0a * (double)d0a - (double)d0 * (double)d0;

        out[0] = (float)(total / (double)n);
    }
}

extern "C" void kernel_launch(void* const* d_in, const int* in_sizes, int n_in,
                              void* d_out, int out_size) {
    const float* in = (const float*)d_in[0];
    const float* tg = (const float*)d_in[1];
    float* out = (float*)d_out;
    int n = in_sizes[0];

    mse_kernel<<<NBLK, NTHR>>>(in, tg, out, n);
}